// round 16
// baseline (speedup 1.0000x reference)
#include <cuda_runtime.h>
#include <math.h>

#define B_ 4
#define L_ 8192
#define D_ 2048
#define H_ 32
#define HD_ 64
#define CHUNK_ 256
#define NT_ 512

#define QSCALE_ 0.1803368801111737f     /* 0.125 * log2(e) */
#define QINV_   5.545177444479562f      /* 1 / QSCALE_ */

__device__ float g_denoms[B_ * L_ * H_];
__device__ unsigned int g_cnt[B_ * (L_ / CHUNK_)];

__device__ __forceinline__ float ex2(float v) {
    float r; asm("ex2.approx.f32 %0, %1;" : "=f"(r) : "f"(v)); return r;
}
__device__ __forceinline__ int swz(int tok) {
    return ((tok >> 4) ^ (tok >> 6)) & 7;
}

__device__ __forceinline__ void load_tile(const float* __restrict__ xh,
                                          int base_tok, float4* __restrict__ tile,
                                          int tid) {
    #pragma unroll
    for (int it = 0; it < 8; it++) {
        const int idx = tid + it * NT_;
        const int tok = idx >> 4;
        const int c   = idx & 15;
        tile[tok * 16 + (c & 8) + ((c & 7) ^ swz(tok))] =
            *reinterpret_cast<const float4*>(xh + (size_t)(base_tok + tok) * D_ + 4 * c);
    }
}

// exp2(score): half-dot (32 dims) + ONE shfl with the partner lane (lane^16).
__device__ __forceinline__ float key_e(const float4* __restrict__ kp, int sw,
                                       const float4* __restrict__ q4) {
    float a0 = 0.f, a1 = 0.f, a2 = 0.f, a3 = 0.f;
    #pragma unroll
    for (int i = 0; i < 8; i++) {
        const float4 k = kp[i ^ sw];
        a0 = fmaf(k.x, q4[i].x, a0); a1 = fmaf(k.y, q4[i].y, a1);
        a2 = fmaf(k.z, q4[i].z, a2); a3 = fmaf(k.w, q4[i].w, a3);
    }
    float s = (a0 + a1) + (a2 + a3);
    s += __shfl_xor_sync(0xffffffffu, s, 16);
    return ex2(s);
}
__device__ __forceinline__ void key_pv(float4* __restrict__ acc,
                                       const float4* __restrict__ kp, int sw, float e) {
    #pragma unroll
    for (int i = 0; i < 8; i++) {
        const float4 k = kp[i ^ sw];
        acc[i].x = fmaf(e, k.x, acc[i].x); acc[i].y = fmaf(e, k.y, acc[i].y);
        acc[i].z = fmaf(e, k.z, acc[i].z); acc[i].w = fmaf(e, k.w, acc[i].w);
    }
}
// first key of an accumulation: ASSIGN tmp (no zero-init of the accumulator)
__device__ __forceinline__ void key_pv0(float4* __restrict__ acc,
                                        const float4* __restrict__ kp, int sw, float e) {
    #pragma unroll
    for (int i = 0; i < 8; i++) {
        const float4 k = kp[i ^ sw];
        acc[i].x = e * k.x; acc[i].y = e * k.y;
        acc[i].z = e * k.z; acc[i].w = e * k.w;
    }
}

// CNT keys at stride STRIDE from kb (serial, R12 form). FIRST=true makes key 0
// initialize (tmp, l) by assignment. Unnormalized exp-sum; no max subtraction
// (scores bounded; every group contains its self key so l >= 1).
template<int CNT, int STRIDE, bool FIRST>
__device__ __forceinline__ void rate_run(const float4* __restrict__ tile, int kb,
                                         int hf8, const float4* __restrict__ q4,
                                         float4* __restrict__ tmp, float& l) {
    #pragma unroll
    for (int j = 0; j < CNT; j++) {
        const int tok = kb + STRIDE * j;
        const float4* kp = tile + tok * 16 + hf8;
        const int sw = swz(tok);
        const float e = key_e(kp, sw, q4);
        if (FIRST && j == 0) {
            l = e;
            key_pv0(tmp, kp, sw, e);
        } else {
            l += e;
            key_pv(tmp, kp, sw, e);
        }
    }
}

// Small private rate (M=2/4): e[] in registers (tiny), normalize directly into
// facc on a second pass (keys reloaded via broadcast LDS). No tmp, no fold.
template<int M>
__device__ __forceinline__ void rate_direct(const float4* __restrict__ tile, int kb,
                                            int hf8, const float4* __restrict__ q4,
                                            float4* __restrict__ facc, float& den) {
    float e[M];
    float l = 0.f;
    #pragma unroll
    for (int j = 0; j < M; j++) {
        const int tok = kb + M * j;
        e[j] = key_e(tile + tok * 16 + hf8, swz(tok), q4);
        l += e[j];
    }
    den += l;
    const float inv = 1.f / l;
    #pragma unroll
    for (int j = 0; j < M; j++) {
        const int tok = kb + M * j;
        key_pv(facc, tile + tok * 16 + hf8, swz(tok), e[j] * inv);
    }
}

__global__ __launch_bounds__(NT_, 1)
void dda_fused_kernel(const float* __restrict__ x, float* __restrict__ out) {
    const int chunk = blockIdx.x;             // 0..31
    const int h     = blockIdx.y;             // 0..31
    const int b     = blockIdx.z;             // 0..3
    const int tid   = threadIdx.x;
    const int w     = tid >> 5;               // warp 0..15
    const int lane  = tid & 31;
    const int qs    = lane & 15;              // query slot
    const int hf    = lane >> 4;              // dim half
    const int hf8   = hf * 8;

    extern __shared__ float4 tile[];          // 256*16 float4 = 65536 B

    const float* xh = x + (size_t)b * L_ * D_ + h * HD_;

    const int t_loc = w + 16 * qs;            // one query per thread (2 lanes/query)
    const int t_glob = chunk * CHUNK_ + t_loc;

    // my half of the query, pre-scaled by 0.125*log2(e)
    float4 q4[8];
    {
        const float* qp = xh + (size_t)t_glob * D_ + 32 * hf;
        #pragma unroll
        for (int i = 0; i < 8; i++) {
            float4 v = *reinterpret_cast<const float4*>(qp + 4 * i);
            v.x *= QSCALE_; v.y *= QSCALE_; v.z *= QSCALE_; v.w *= QSCALE_;
            q4[i] = v;
        }
    }

    float4 facc[8];
    float  den;
    float4 tmp[8];
    float  l;

    // ---- rate 5 (m=32): unnormalized exp-sum over the 4 chunks of the
    // 1024-window; own chunk LAST so the tile stays resident for rates 4..0.
    {
        const int rr   = w + 16 * (qs & 1);
        const int wch0 = chunk & ~3;
        const int myc  = chunk & 3;
        // first chunk (cc = 1): initializes tmp, l by assignment
        {
            const int c = wch0 + ((myc + 1) & 3);
            __syncthreads();
            load_tile(xh, c * CHUNK_, tile, tid);
            __syncthreads();
            rate_run<8, 32, true>(tile, rr, hf8, q4, tmp, l);
        }
        for (int cc = 2; cc <= 4; cc++) {
            const int c = wch0 + ((myc + cc) & 3);
            __syncthreads();
            load_tile(xh, c * CHUNK_, tile, tid);
            __syncthreads();
            rate_run<8, 32, false>(tile, rr, hf8, q4, tmp, l);
        }
        den = l;
        const float inv = 1.f / l;
        #pragma unroll
        for (int i = 0; i < 8; i++) {   // facc initialized here (no zero-init)
            facc[i].x = inv * tmp[i].x; facc[i].y = inv * tmp[i].y;
            facc[i].z = inv * tmp[i].z; facc[i].w = inv * tmp[i].w;
        }
    }

    // ---- rate M=16 (shared by 16 queries) and M=8 (shared by 4): tmp path
    #pragma unroll
    for (int r = 0; r < 2; r++) {
        if (r == 0) rate_run<16, 16, true>(tile, w, hf8, q4, tmp, l);
        else        rate_run<8, 8, true>(tile, (t_loc & ~63) + (w & 7), hf8, q4, tmp, l);
        den += l;
        const float inv = 1.f / l;
        #pragma unroll
        for (int i = 0; i < 8; i++) {
            facc[i].x = fmaf(inv, tmp[i].x, facc[i].x);
            facc[i].y = fmaf(inv, tmp[i].y, facc[i].y);
            facc[i].z = fmaf(inv, tmp[i].z, facc[i].z);
            facc[i].w = fmaf(inv, tmp[i].w, facc[i].w);
        }
    }

    // ---- rates M=4, M=2: tiny e[] two-phase straight into facc
    rate_direct<4>(tile, (t_loc & ~15) + (w & 3), hf8, q4, facc, den);
    rate_direct<2>(tile, (t_loc & ~3) + (w & 1), hf8, q4, facc, den);

    // ---- rate 0: self key, prob = 1. score*log2e = |q'|^2 / QSCALE_.
    {
        float s = 0.f;
        #pragma unroll
        for (int i = 0; i < 8; i++) {
            s = fmaf(q4[i].x, q4[i].x, s); s = fmaf(q4[i].y, q4[i].y, s);
            s = fmaf(q4[i].z, q4[i].z, s); s = fmaf(q4[i].w, q4[i].w, s);
        }
        s += __shfl_xor_sync(0xffffffffu, s, 16);
        den += ex2(s * QINV_);
        #pragma unroll
        for (int i = 0; i < 8; i++) {     // out += q (unscaled) = q' / QSCALE_
            facc[i].x = fmaf(QINV_, q4[i].x, facc[i].x);
            facc[i].y = fmaf(QINV_, q4[i].y, facc[i].y);
            facc[i].z = fmaf(QINV_, q4[i].z, facc[i].z);
            facc[i].w = fmaf(QINV_, q4[i].w, facc[i].w);
        }
    }

    // ---- writes
    if (hf == 0)
        g_denoms[((size_t)b * L_ + t_glob) * H_ + h] = den;
    {
        float* op = out + (size_t)b * L_ * D_ + (size_t)t_glob * D_ + h * HD_ + 32 * hf;
        #pragma unroll
        for (int i = 0; i < 8; i++)
            *reinterpret_cast<float4*>(op + 4 * i) = facc[i];
    }

    // ---- last CTA per (b,chunk): head-softmax combine
    __threadfence();
    __shared__ unsigned int s_last;
    __syncthreads();
    if (tid == 0)
        s_last = (atomicInc(&g_cnt[b * (L_ / CHUNK_) + chunk], H_ - 1) == H_ - 1);
    __syncthreads();
    if (s_last) {
        const int k = lane;
        for (int t0 = w; t0 < CHUNK_; t0 += 16) {
            const size_t tok = (size_t)b * L_ + chunk * CHUNK_ + t0;
            const float v = __ldcg(&g_denoms[tok * H_ + k]);   // lane = head
            float mx = v;
            #pragma unroll
            for (int off = 16; off > 0; off >>= 1)
                mx = fmaxf(mx, __shfl_xor_sync(0xffffffffu, mx, off));
            const float e = __expf(v - mx);
            float sum = e;
            #pragma unroll
            for (int off = 16; off > 0; off >>= 1)
                sum += __shfl_xor_sync(0xffffffffu, sum, off);
            const float wgt = e / sum;
            float4* row = reinterpret_cast<float4*>(out + tok * D_);
            #pragma unroll
            for (int it = 0; it < 16; it++) {
                const int idx = k + 32 * it;
                const float ww = __shfl_sync(0xffffffffu, wgt, idx >> 4);
                float4 vv = __ldcg(&row[idx]);
                vv.x *= ww; vv.y *= ww; vv.z *= ww; vv.w *= ww;
                row[idx] = vv;
            }
        }
    }
}

extern "C" void kernel_launch(void* const* d_in, const int* in_sizes, int n_in,
                              void* d_out, int out_size) {
    const float* x = (const float*)d_in[0];
    float* out = (float*)d_out;

    const int smem_bytes = CHUNK_ * 16 * (int)sizeof(float4);   // 65536 B
    cudaFuncSetAttribute(dda_fused_kernel,
                         cudaFuncAttributeMaxDynamicSharedMemorySize, smem_bytes);

    dim3 grid(L_ / CHUNK_, H_, B_);
    dda_fused_kernel<<<grid, NT_, smem_bytes>>>(x, out);
}

// round 17
// speedup vs baseline: 1.1647x; 1.1647x over previous
#include <cuda_runtime.h>
#include <math.h>

#define B_ 4
#define L_ 8192
#define D_ 2048
#define H_ 32
#define HD_ 64
#define CHUNK_ 256
#define NT_ 512

#define QSCALE_ 0.1803368801111737f     /* 0.125 * log2(e) */
#define QINV_   5.545177444479562f      /* 1 / QSCALE_ */

__device__ float g_denoms[B_ * L_ * H_];
__device__ unsigned int g_cnt[B_ * (L_ / CHUNK_)];

__device__ __forceinline__ float ex2(float v) {
    float r; asm("ex2.approx.f32 %0, %1;" : "=f"(r) : "f"(v)); return r;
}
// column swizzle within each 8-float4 half; decorrelates banks for toks that
// differ in bits 4..7 (the private-rate strides). Same tok -> same sw, so all
// broadcast patterns are unaffected.
__device__ __forceinline__ int swz(int tok) {
    return ((tok >> 4) ^ (tok >> 6)) & 7;
}

__device__ __forceinline__ void load_tile(const float* __restrict__ xh,
                                          int base_tok, float4* __restrict__ tile,
                                          int tid) {
    #pragma unroll
    for (int it = 0; it < 8; it++) {
        const int idx = tid + it * NT_;
        const int tok = idx >> 4;
        const int c   = idx & 15;
        tile[tok * 16 + (c & 8) + ((c & 7) ^ swz(tok))] =
            *reinterpret_cast<const float4*>(xh + (size_t)(base_tok + tok) * D_ + 4 * c);
    }
}

// exp2(score) for this thread's query vs key tok. Half-dot (32 dims) + ONE
// shfl to combine with the partner lane (lane^16); both lanes get e.
__device__ __forceinline__ float key_e(const float4* __restrict__ kp, int sw,
                                       const float4* __restrict__ q4) {
    float a0 = 0.f, a1 = 0.f, a2 = 0.f, a3 = 0.f;
    #pragma unroll
    for (int i = 0; i < 8; i++) {
        const float4 k = kp[i ^ sw];
        a0 = fmaf(k.x, q4[i].x, a0); a1 = fmaf(k.y, q4[i].y, a1);
        a2 = fmaf(k.z, q4[i].z, a2); a3 = fmaf(k.w, q4[i].w, a3);
    }
    float s = (a0 + a1) + (a2 + a3);
    s += __shfl_xor_sync(0xffffffffu, s, 16);
    return ex2(s);
}
// PV: reload key (broadcast LDS) and accumulate e * key into tmp.
__device__ __forceinline__ void key_pv(float4* __restrict__ acc,
                                       const float4* __restrict__ kp, int sw, float e) {
    #pragma unroll
    for (int i = 0; i < 8; i++) {
        const float4 k = kp[i ^ sw];
        acc[i].x = fmaf(e, k.x, acc[i].x); acc[i].y = fmaf(e, k.y, acc[i].y);
        acc[i].z = fmaf(e, k.z, acc[i].z); acc[i].w = fmaf(e, k.w, acc[i].w);
    }
}

// CNT keys at stride STRIDE from per-lane base kb; unnormalized exp-sum into
// (tmp, l). No max subtraction (scores bounded; every group has its self key).
template<int CNT, int STRIDE>
__device__ __forceinline__ void rate_run(const float4* __restrict__ tile, int kb,
                                         int hf8, const float4* __restrict__ q4,
                                         float4* __restrict__ tmp, float& l) {
    #pragma unroll
    for (int j = 0; j < CNT; j++) {
        const int tok = kb + STRIDE * j;
        const float4* kp = tile + tok * 16 + hf8;
        const int sw = swz(tok);
        const float e = key_e(kp, sw, q4);
        l += e;
        key_pv(tmp, kp, sw, e);
    }
}

__global__ __launch_bounds__(NT_, 1)
void dda_fused_kernel(const float* __restrict__ x, float* __restrict__ out) {
    const int chunk = blockIdx.x;             // 0..31
    const int h     = blockIdx.y;             // 0..31
    const int b     = blockIdx.z;             // 0..3
    const int tid   = threadIdx.x;
    const int w     = tid >> 5;               // warp 0..15
    const int lane  = tid & 31;
    const int qs    = lane & 15;              // query slot
    const int hf    = lane >> 4;              // dim half (0: dims 0..31)
    const int hf8   = hf * 8;

    extern __shared__ float4 tile[];          // 256*16 float4 = 65536 B

    const float* xh = x + (size_t)b * L_ * D_ + h * HD_;

    const int t_loc = w + 16 * qs;            // one query per thread (2 lanes/query)
    const int t_glob = chunk * CHUNK_ + t_loc;

    // my half of the query, pre-scaled by 0.125*log2(e)
    float4 q4[8];
    {
        const float* qp = xh + (size_t)t_glob * D_ + 32 * hf;
        #pragma unroll
        for (int i = 0; i < 8; i++) {
            float4 v = *reinterpret_cast<const float4*>(qp + 4 * i);
            v.x *= QSCALE_; v.y *= QSCALE_; v.z *= QSCALE_; v.w *= QSCALE_;
            q4[i] = v;
        }
    }

    float4 facc[8];
    #pragma unroll
    for (int i = 0; i < 8; i++) facc[i] = make_float4(0.f, 0.f, 0.f, 0.f);
    float den = 0.f;

    float4 tmp[8];
    float  l;

    // ---- rate 5 (m=32): unnormalized exp-sum over the 4 chunks of the
    // 1024-window; own chunk LAST so the tile stays resident for rates 4..0.
    // Key residue = t mod 32 = w + 16*(qs&1): one LDS serves 8 queries.
    {
        #pragma unroll
        for (int i = 0; i < 8; i++) tmp[i] = make_float4(0.f, 0.f, 0.f, 0.f);
        l = 0.f;
        const int rr   = w + 16 * (qs & 1);
        const int wch0 = chunk & ~3;
        const int myc  = chunk & 3;
        for (int cc = 1; cc <= 4; cc++) {
            const int c = wch0 + ((myc + cc) & 3);
            __syncthreads();
            load_tile(xh, c * CHUNK_, tile, tid);
            __syncthreads();
            rate_run<8, 32>(tile, rr, hf8, q4, tmp, l);
        }
        den += l;
        const float inv = 1.f / l;
        #pragma unroll
        for (int i = 0; i < 8; i++) {
            facc[i].x = fmaf(inv, tmp[i].x, facc[i].x);
            facc[i].y = fmaf(inv, tmp[i].y, facc[i].y);
            facc[i].z = fmaf(inv, tmp[i].z, facc[i].z);
            facc[i].w = fmaf(inv, tmp[i].w, facc[i].w);
        }
    }

    // ---- rates 4..1 on the resident own-chunk tile; temp reused per rate.
    #pragma unroll
    for (int r = 0; r < 4; r++) {
        #pragma unroll
        for (int i = 0; i < 8; i++) tmp[i] = make_float4(0.f, 0.f, 0.f, 0.f);
        l = 0.f;
        if (r == 0)      rate_run<16, 16>(tile, w, hf8, q4, tmp, l);                       // keys shared by 16 queries
        else if (r == 1) rate_run<8, 8>(tile, (t_loc & ~63) + (w & 7), hf8, q4, tmp, l);   // shared by 4
        else if (r == 2) rate_run<4, 4>(tile, (t_loc & ~15) + (w & 3), hf8, q4, tmp, l);   // private
        else             rate_run<2, 2>(tile, (t_loc & ~3) + (w & 1), hf8, q4, tmp, l);    // private
        den += l;
        const float inv = 1.f / l;
        #pragma unroll
        for (int i = 0; i < 8; i++) {
            facc[i].x = fmaf(inv, tmp[i].x, facc[i].x);
            facc[i].y = fmaf(inv, tmp[i].y, facc[i].y);
            facc[i].z = fmaf(inv, tmp[i].z, facc[i].z);
            facc[i].w = fmaf(inv, tmp[i].w, facc[i].w);
        }
    }

    // ---- rate 0: self key, prob = 1. score*log2e = |q'|^2 / QSCALE_.
    {
        float s = 0.f;
        #pragma unroll
        for (int i = 0; i < 8; i++) {
            s = fmaf(q4[i].x, q4[i].x, s); s = fmaf(q4[i].y, q4[i].y, s);
            s = fmaf(q4[i].z, q4[i].z, s); s = fmaf(q4[i].w, q4[i].w, s);
        }
        s += __shfl_xor_sync(0xffffffffu, s, 16);
        den += ex2(s * QINV_);
        #pragma unroll
        for (int i = 0; i < 8; i++) {     // out += q (unscaled) = q' / QSCALE_
            facc[i].x = fmaf(QINV_, q4[i].x, facc[i].x);
            facc[i].y = fmaf(QINV_, q4[i].y, facc[i].y);
            facc[i].z = fmaf(QINV_, q4[i].z, facc[i].z);
            facc[i].w = fmaf(QINV_, q4[i].w, facc[i].w);
        }
    }

    // ---- writes
    if (hf == 0)
        g_denoms[((size_t)b * L_ + t_glob) * H_ + h] = den;
    {
        float* op = out + (size_t)b * L_ * D_ + (size_t)t_glob * D_ + h * HD_ + 32 * hf;
        #pragma unroll
        for (int i = 0; i < 8; i++)
            *reinterpret_cast<float4*>(op + 4 * i) = facc[i];
    }

    // ---- last CTA per (b,chunk): head-softmax combine
    __threadfence();
    __shared__ unsigned int s_last;
    __syncthreads();
    if (tid == 0)
        s_last = (atomicInc(&g_cnt[b * (L_ / CHUNK_) + chunk], H_ - 1) == H_ - 1);
    __syncthreads();
    if (s_last) {
        const int k = lane;
        for (int t0 = w; t0 < CHUNK_; t0 += 16) {
            const size_t tok = (size_t)b * L_ + chunk * CHUNK_ + t0;
            const float v = __ldcg(&g_denoms[tok * H_ + k]);   // lane = head
            float mx = v;
            #pragma unroll
            for (int off = 16; off > 0; off >>= 1)
                mx = fmaxf(mx, __shfl_xor_sync(0xffffffffu, mx, off));
            const float e = __expf(v - mx);
            float sum = e;
            #pragma unroll
            for (int off = 16; off > 0; off >>= 1)
                sum += __shfl_xor_sync(0xffffffffu, sum, off);
            const float wgt = e / sum;
            float4* row = reinterpret_cast<float4*>(out + tok * D_);
            #pragma unroll
            for (int it = 0; it < 16; it++) {
                const int idx = k + 32 * it;
                const float ww = __shfl_sync(0xffffffffu, wgt, idx >> 4);
                float4 vv = __ldcg(&row[idx]);
                vv.x *= ww; vv.y *= ww; vv.z *= ww; vv.w *= ww;
                row[idx] = vv;
            }
        }
    }
}

extern "C" void kernel_launch(void* const* d_in, const int* in_sizes, int n_in,
                              void* d_out, int out_size) {
    const float* x = (const float*)d_in[0];
    float* out = (float*)d_out;

    const int smem_bytes = CHUNK_ * 16 * (int)sizeof(float4);   // 65536 B
    cudaFuncSetAttribute(dda_fused_kernel,
                         cudaFuncAttributeMaxDynamicSharedMemorySize, smem_bytes);

    dim3 grid(L_ / CHUNK_, H_, B_);
    dda_fused_kernel<<<grid, NT_, smem_bytes>>>(x, out);
}